// round 7
// baseline (speedup 1.0000x reference)
#include <cuda_runtime.h>
#include <cuda_bf16.h>
#include <cstdint>

typedef __nv_bfloat16 bf16;

// ---------------- scratch ----------------
__device__ bf16 g_Ah [256 * 4096], g_Al [256 * 4096];
__device__ bf16 g_Ah2[256 * 4096], g_Al2[256 * 4096];
__device__ bf16 g_Ah3[256 * 4096], g_Al3[256 * 4096];
__device__ bf16 g_W1h[4096u * 4096u], g_W1l[4096u * 4096u];
__device__ bf16 g_W2h[4096u * 4096u], g_W2l[4096u * 4096u];
__device__ bf16 g_W3h[256 * 4096],   g_W3l[256 * 4096];
__device__ float g_p3 [16 * 256 * 256];
__device__ float g_pts[256 * 200];

// ---------------- helpers ----------------
__device__ __forceinline__ float sig_apx(float a) {
    float r; asm("tanh.approx.f32 %0,%1;" : "=f"(r) : "f"(a * 0.5f));
    return fmaf(0.5f, r, 0.5f);
}
__device__ __forceinline__ void split_bf16(float v, bf16& h, bf16& l) {
    h = __float2bfloat16(v);
    l = __float2bfloat16(v - __bfloat162float(h));
}
__device__ __forceinline__ void mma16816(float* c, const uint32_t* a, const uint32_t* b) {
    asm volatile("mma.sync.aligned.m16n8k16.row.col.f32.bf16.bf16.f32 "
        "{%0,%1,%2,%3}, {%4,%5,%6,%7}, {%8,%9}, {%0,%1,%2,%3};"
        : "+f"(c[0]), "+f"(c[1]), "+f"(c[2]), "+f"(c[3])
        : "r"(a[0]), "r"(a[1]), "r"(a[2]), "r"(a[3]), "r"(b[0]), "r"(b[1]));
}
__device__ __forceinline__ void ldsm4(uint32_t* r, uint32_t addr) {
    asm volatile("ldmatrix.sync.aligned.m8n8.x4.shared.b16 {%0,%1,%2,%3}, [%4];"
        : "=r"(r[0]), "=r"(r[1]), "=r"(r[2]), "=r"(r[3]) : "r"(addr));
}
__device__ __forceinline__ void cpasync16(uint32_t dst, const void* src) {
    asm volatile("cp.async.cg.shared.global [%0], [%1], 16;" :: "r"(dst), "l"(src) : "memory");
}
__device__ __forceinline__ void cpcommit() {
    asm volatile("cp.async.commit_group;" ::: "memory");
}
template<int N> __device__ __forceinline__ void cpwait() {
    asm volatile("cp.async.wait_group %0;" :: "n"(N) : "memory");
}

// ---------------- ECT body (256 threads) ----------------
struct EctSm {
    float xs[200];
    float Vs[128];
    float lins[64];
    float e2[2][4096];
    unsigned char cnt2[2][4096];
    float red[256];
};
#define PREP_SMEM (sizeof(EctSm))

__device__ void ect_body(int g, int tid, const float* __restrict__ pts,
                         const float* __restrict__ V, const float* __restrict__ lin,
                         float* __restrict__ outf, bf16* __restrict__ outh,
                         bf16* __restrict__ outl, char* sm)
{
    EctSm& S = *reinterpret_cast<EctSm*>(sm);
    if (tid < 64)  S.lins[tid] = lin[tid];
    if (tid < 128) S.Vs[tid] = V[tid];
    if (tid < 100) {
        float2 p = reinterpret_cast<const float2*>(pts)[g * 100 + tid];
        S.xs[2 * tid] = p.x; S.xs[2 * tid + 1] = p.y;
    }
    for (int i = tid; i < 8192; i += 256) (&S.e2[0][0])[i] = 0.0f;
    for (int i = tid; i < 2048; i += 256) reinterpret_cast<int*>(S.cnt2)[i] = 0;
    __syncthreads();

    if (tid < 128) {
        const int t = tid & 63, half = tid >> 6;
        const float vx = S.Vs[t], vy = S.Vs[64 + t];
        float* e = &S.e2[half][t];
        unsigned char* cc = &S.cnt2[half][t];
        const int nbeg = half * 50;
        for (int n = 0; n < 50; ++n) {
            const float x0 = S.xs[2 * (nbeg + n)], x1 = S.xs[2 * (nbeg + n) + 1];
            const float nh = fmaf(x0, vx, x1 * vy);
            const int kf = __float2int_rd((nh + 1.0f) * 31.5f);
            if (kf >= 0 && kf < 64)         e[kf * 64]       += sig_apx(500.0f * (S.lins[kf] - nh));
            if (kf + 1 >= 0 && kf + 1 < 64) e[(kf + 1) * 64] += sig_apx(500.0f * (S.lins[kf + 1] - nh));
            int s = kf + 2; if (s < 0) s = 0;
            if (s < 64) cc[s * 64] = (unsigned char)(cc[s * 64] + 1);
        }
    }
    __syncthreads();

    if (tid < 64) {
        float run = 0.0f;
        for (int k = 0; k < 64; ++k) {
            const int o = k * 64 + tid;
            run += (float)(S.cnt2[0][o] + S.cnt2[1][o]);
            S.e2[0][o] = S.e2[0][o] + S.e2[1][o] + run;
        }
    }
    __syncthreads();

    float mx = 0.0f;
    for (int i = tid; i < 4096; i += 256) mx = fmaxf(mx, S.e2[0][i]);
    S.red[tid] = mx; __syncthreads();
    for (int off = 128; off > 0; off >>= 1) {
        if (tid < off) S.red[tid] = fmaxf(S.red[tid], S.red[tid + off]);
        __syncthreads();
    }
    const float inv = 1.0f / S.red[0];
    for (int i = tid; i < 4096; i += 256) {
        float v = S.e2[0][i] * inv;
        if (outf) outf[(long)g * 4096 + i] = v;
        if (outh) {
            bf16 h, l; split_bf16(v, h, l);
            outh[(long)g * 4096 + i] = h;
            outl[(long)g * 4096 + i] = l;
        }
    }
}

// ---------------- transpose body ----------------
__device__ void transpose_body(int kt, int ntile, int tid, const float* __restrict__ W,
                               int Wn, bf16* __restrict__ Th, bf16* __restrict__ Tl, char* sm)
{
    float (*s)[65] = reinterpret_cast<float(*)[65]>(sm);
    const int k0 = kt * 64, n0 = ntile * 64;
    const int r = tid >> 4, c4 = (tid & 15) * 4;
    #pragma unroll
    for (int p = 0; p < 4; ++p) {
        const int kk = p * 16 + r;
        float4 v;
        if (Wn == 4096) {
            v = *reinterpret_cast<const float4*>(W + (long)(k0 + kk) * 4096 + n0 + c4);
        } else {
            float t0 = 0, t1 = 0, t2 = 0, t3 = 0;
            const long base = (long)(k0 + kk) * 200;
            if (n0 + c4 + 0 < 200) t0 = W[base + n0 + c4 + 0];
            if (n0 + c4 + 1 < 200) t1 = W[base + n0 + c4 + 1];
            if (n0 + c4 + 2 < 200) t2 = W[base + n0 + c4 + 2];
            if (n0 + c4 + 3 < 200) t3 = W[base + n0 + c4 + 3];
            v = make_float4(t0, t1, t2, t3);
        }
        s[kk][c4] = v.x; s[kk][c4 + 1] = v.y; s[kk][c4 + 2] = v.z; s[kk][c4 + 3] = v.w;
    }
    __syncthreads();
    #pragma unroll
    for (int q = 0; q < 2; ++q) {
        const int idx = tid + 256 * q;
        const int n = idx >> 3, kg = idx & 7;
        uint4 uh, ul;
        __nv_bfloat162* ph = reinterpret_cast<__nv_bfloat162*>(&uh);
        __nv_bfloat162* pl = reinterpret_cast<__nv_bfloat162*>(&ul);
        #pragma unroll
        for (int j = 0; j < 4; ++j) {
            bf16 h0, l0, h1, l1;
            split_bf16(s[kg * 8 + 2 * j][n],     h0, l0);
            split_bf16(s[kg * 8 + 2 * j + 1][n], h1, l1);
            ph[j] = __halves2bfloat162(h0, h1);
            pl[j] = __halves2bfloat162(l0, l1);
        }
        const long o = (long)(n0 + n) * 4096 + k0 + kg * 8;
        *reinterpret_cast<uint4*>(Th + o) = uh;
        *reinterpret_cast<uint4*>(Tl + o) = ul;
    }
}

// ---------------- fused prep ----------------
__global__ void __launch_bounds__(256) prep_all(const float* __restrict__ x,
    const float* __restrict__ V, const float* __restrict__ lin,
    const float* __restrict__ W1, const float* __restrict__ W2, const float* __restrict__ W3,
    bf16* W1h, bf16* W1l, bf16* W2h, bf16* W2l, bf16* W3h, bf16* W3l,
    bf16* Ah, bf16* Al)
{
    extern __shared__ char sm[];
    int b = blockIdx.x;
    const int tid = threadIdx.x;
    if (b < 4096)       transpose_body(b & 63, b >> 6, tid, W1, 4096, W1h, W1l, sm);
    else if (b < 8192) { b -= 4096; transpose_body(b & 63, b >> 6, tid, W2, 4096, W2h, W2l, sm); }
    else if (b < 8448) { b -= 8192; transpose_body(b & 63, b >> 6, tid, W3,  200, W3h, W3l, sm); }
    else                ect_body(b - 8448, tid, x, V, lin, nullptr, Ah, Al, sm);
}

__global__ void __launch_bounds__(256) ect_final(const float* __restrict__ pts,
    const float* __restrict__ V, const float* __restrict__ lin, float* __restrict__ out)
{
    extern __shared__ char sm[];
    ect_body(blockIdx.x, threadIdx.x, pts, V, lin, out, nullptr, nullptr, sm);
}

// ---------------- HMMA GEMM: 4-stage cp.async, 1 barrier/ktile ----------------
// CTA 64x128, BK=64, 8 warps (2x4), warp 32x32, SW(16B-xor) smem.
#define STG 49152
#define NSTAGE 4
#define GMEM_SM (NSTAGE * STG)

template<int KT, bool TANH>
__global__ void __launch_bounds__(256) gemm_mma(const bf16* __restrict__ Ah,
                                                const bf16* __restrict__ Al,
                                                const bf16* __restrict__ Bh,
                                                const bf16* __restrict__ Bl,
                                                const float* __restrict__ bias,
                                                bf16* __restrict__ oH,
                                                bf16* __restrict__ oL,
                                                float* __restrict__ oP)
{
    extern __shared__ __align__(16) char dsm[];
    const uint32_t smem0 = (uint32_t)__cvta_generic_to_shared(dsm);
    const int tid = threadIdx.x;
    const int lane = tid & 31, wid = tid >> 5;
    const int wm = wid >> 2, wn = wid & 3;
    const int m0 = blockIdx.x * 64, n0 = blockIdx.y * 128;
    const long kOff = TANH ? 0 : (long)blockIdx.z * (KT * 64);

    const int r0 = tid >> 3, kq = tid & 7;
    const uint32_t dsw = (uint32_t)(r0 * 128 + ((kq * 16) ^ ((r0 & 7) << 4)));
    const bf16* pAh = Ah + (long)(m0 + r0) * 4096 + kOff + kq * 8;
    const bf16* pAl = Al + (long)(m0 + r0) * 4096 + kOff + kq * 8;
    const bf16* pBh = Bh + (long)(n0 + r0) * 4096 + kOff + kq * 8;
    const bf16* pBl = Bl + (long)(n0 + r0) * 4096 + kOff + kq * 8;

    float acc[2][4][4];
    #pragma unroll
    for (int a = 0; a < 2; ++a)
        #pragma unroll
        for (int b = 0; b < 4; ++b)
            #pragma unroll
            for (int c = 0; c < 4; ++c) acc[a][b][c] = 0.0f;

    const int lr = lane & 7, lt = lane >> 3;
    const uint32_t aRow = (uint32_t)((wm * 32 + ((lt & 1) << 3) + lr) * 128);
    const int aK = (lt >> 1) * 16;
    const uint32_t bRow = (uint32_t)((wn * 32 + ((lt >> 1) << 3) + lr) * 128);
    const int bK = (lt & 1) * 16;
    const int sw = lr << 4;

    // load one stage's tiles via cp.async
    auto load_stage = [&](int stg, int kt) {
        const uint32_t st = smem0 + stg * STG;
        const long g = (long)kt * 64;
        #pragma unroll
        for (int i = 0; i < 2; ++i) {
            cpasync16(st + dsw + i * 32 * 128,        pAh + g + (long)i * 32 * 4096);
            cpasync16(st + 8192 + dsw + i * 32 * 128, pAl + g + (long)i * 32 * 4096);
        }
        #pragma unroll
        for (int i = 0; i < 4; ++i) {
            cpasync16(st + 16384 + dsw + i * 32 * 128, pBh + g + (long)i * 32 * 4096);
            cpasync16(st + 32768 + dsw + i * 32 * 128, pBl + g + (long)i * 32 * 4096);
        }
    };

    // prologue: fill stages 0..2 (guard for small KT)
    #pragma unroll
    for (int s = 0; s < NSTAGE - 1; ++s) {
        if (s < KT) load_stage(s, s);
        cpcommit();
    }

    for (int kt = 0; kt < KT; ++kt) {
        if (kt + NSTAGE - 1 < KT) load_stage((kt + NSTAGE - 1) & (NSTAGE - 1), kt + NSTAGE - 1);
        cpcommit();
        cpwait<NSTAGE - 1>();
        __syncthreads();

        const uint32_t st = smem0 + (kt & (NSTAGE - 1)) * STG;
        #pragma unroll
        for (int ks = 0; ks < 4; ++ks) {
            const int ka = (ks * 32 + aK) ^ sw;
            const int kb = (ks * 32 + bK) ^ sw;
            uint32_t fAh[2][4], fAl[2][4], fBh[2][4], fBl[2][4];
            ldsm4(fAh[0], st + aRow + ka);
            ldsm4(fAh[1], st + aRow + 16 * 128 + ka);
            ldsm4(fAl[0], st + 8192 + aRow + ka);
            ldsm4(fAl[1], st + 8192 + aRow + 16 * 128 + ka);
            ldsm4(fBh[0], st + 16384 + bRow + kb);
            ldsm4(fBh[1], st + 16384 + bRow + 16 * 128 + kb);
            ldsm4(fBl[0], st + 32768 + bRow + kb);
            ldsm4(fBl[1], st + 32768 + bRow + 16 * 128 + kb);
            #pragma unroll
            for (int mt = 0; mt < 2; ++mt)
                #pragma unroll
                for (int nt = 0; nt < 4; ++nt) {
                    const uint32_t* bh = &fBh[nt >> 1][(nt & 1) * 2];
                    const uint32_t* bl = &fBl[nt >> 1][(nt & 1) * 2];
                    mma16816(acc[mt][nt], fAh[mt], bh);
                    mma16816(acc[mt][nt], fAh[mt], bl);
                    mma16816(acc[mt][nt], fAl[mt], bh);
                }
        }
    }

    const int laneR = lane >> 2;
    #pragma unroll
    for (int mt = 0; mt < 2; ++mt)
        #pragma unroll
        for (int nt = 0; nt < 4; ++nt) {
            const int rr = m0 + wm * 32 + mt * 16 + laneR;
            const int nc = n0 + wn * 32 + nt * 8 + 2 * (lane & 3);
            if (TANH) {
                const float b0 = bias[nc], b1 = bias[nc + 1];
                float v00 = tanhf(acc[mt][nt][0] + b0);
                float v01 = tanhf(acc[mt][nt][1] + b1);
                float v10 = tanhf(acc[mt][nt][2] + b0);
                float v11 = tanhf(acc[mt][nt][3] + b1);
                bf16 h00, l00, h01, l01, h10, l10, h11, l11;
                split_bf16(v00, h00, l00); split_bf16(v01, h01, l01);
                split_bf16(v10, h10, l10); split_bf16(v11, h11, l11);
                *(__nv_bfloat162*)(oH + (long)rr * 4096 + nc)       = __halves2bfloat162(h00, h01);
                *(__nv_bfloat162*)(oH + (long)(rr + 8) * 4096 + nc) = __halves2bfloat162(h10, h11);
                *(__nv_bfloat162*)(oL + (long)rr * 4096 + nc)       = __halves2bfloat162(l00, l01);
                *(__nv_bfloat162*)(oL + (long)(rr + 8) * 4096 + nc) = __halves2bfloat162(l10, l11);
            } else {
                float* P = oP + (long)blockIdx.z * 65536;
                *(float2*)(P + (long)rr * 256 + nc)       = make_float2(acc[mt][nt][0], acc[mt][nt][1]);
                *(float2*)(P + (long)(rr + 8) * 256 + nc) = make_float2(acc[mt][nt][2], acc[mt][nt][3]);
            }
        }
}

// ---------------- reduce ----------------
__global__ void reduce_pts(const float* __restrict__ P, const float* __restrict__ b3,
                           float* __restrict__ pts, float* __restrict__ otail)
{
    const int i = blockIdx.x * 256 + threadIdx.x;
    const int m = i >> 8, n = i & 255;
    if (n >= 200) return;
    float s = b3[n];
    #pragma unroll
    for (int zz = 0; zz < 16; ++zz) s += P[zz * 65536 + i];
    pts[m * 200 + n] = s;
    otail[m * 200 + n] = s;
}

// ---------------- launch ----------------
extern "C" void kernel_launch(void* const* d_in, const int* in_sizes, int n_in,
                              void* d_out, int out_size)
{
    const float* x   = (const float*)d_in[0];
    const float* V   = (const float*)d_in[2];
    const float* lin = (const float*)d_in[3];
    const float* W1  = (const float*)d_in[4];
    const float* b1  = (const float*)d_in[5];
    const float* W2  = (const float*)d_in[6];
    const float* b2  = (const float*)d_in[7];
    const float* W3  = (const float*)d_in[8];
    const float* b3  = (const float*)d_in[9];
    float* out = (float*)d_out;

    bf16 *Ah, *Al, *Ah2, *Al2, *Ah3, *Al3, *W1h, *W1l, *W2h, *W2l, *W3h, *W3l;
    float *p3, *pts;
    cudaGetSymbolAddress((void**)&Ah,  g_Ah);
    cudaGetSymbolAddress((void**)&Al,  g_Al);
    cudaGetSymbolAddress((void**)&Ah2, g_Ah2);
    cudaGetSymbolAddress((void**)&Al2, g_Al2);
    cudaGetSymbolAddress((void**)&Ah3, g_Ah3);
    cudaGetSymbolAddress((void**)&Al3, g_Al3);
    cudaGetSymbolAddress((void**)&W1h, g_W1h);
    cudaGetSymbolAddress((void**)&W1l, g_W1l);
    cudaGetSymbolAddress((void**)&W2h, g_W2h);
    cudaGetSymbolAddress((void**)&W2l, g_W2l);
    cudaGetSymbolAddress((void**)&W3h, g_W3h);
    cudaGetSymbolAddress((void**)&W3l, g_W3l);
    cudaGetSymbolAddress((void**)&p3,  g_p3);
    cudaGetSymbolAddress((void**)&pts, g_pts);

    const int prep_sm = (int)PREP_SMEM;
    cudaFuncSetAttribute(prep_all,  cudaFuncAttributeMaxDynamicSharedMemorySize, prep_sm);
    cudaFuncSetAttribute(ect_final, cudaFuncAttributeMaxDynamicSharedMemorySize, prep_sm);
    cudaFuncSetAttribute(gemm_mma<64, true>,  cudaFuncAttributeMaxDynamicSharedMemorySize, GMEM_SM);
    cudaFuncSetAttribute(gemm_mma<4, false>,  cudaFuncAttributeMaxDynamicSharedMemorySize, GMEM_SM);

    prep_all<<<8704, 256, prep_sm>>>(x, V, lin, W1, W2, W3,
                                     W1h, W1l, W2h, W2l, W3h, W3l, Ah, Al);

    gemm_mma<64, true><<<dim3(4, 32), 256, GMEM_SM>>>(Ah,  Al,  W1h, W1l, b1, Ah2, Al2, nullptr);
    gemm_mma<64, true><<<dim3(4, 32), 256, GMEM_SM>>>(Ah2, Al2, W2h, W2l, b2, Ah3, Al3, nullptr);
    gemm_mma<4, false><<<dim3(4, 2, 16), 256, GMEM_SM>>>(Ah3, Al3, W3h, W3l, nullptr, nullptr, nullptr, p3);

    reduce_pts<<<256, 256>>>(p3, b3, pts, out + 256 * 64 * 64);
    ect_final<<<256, 256, prep_sm>>>(pts, V, lin, out);
}

// round 8
// speedup vs baseline: 1.2585x; 1.2585x over previous
#include <cuda_runtime.h>
#include <cuda_fp16.h>
#include <cstdint>

typedef __half f16;

// ---------------- scratch ----------------
__device__ f16 g_Ah [256 * 4096], g_Al [256 * 4096];
__device__ f16 g_Ah2[256 * 4096], g_Al2[256 * 4096];
__device__ f16 g_Ah3[256 * 4096], g_Al3[256 * 4096];
__device__ f16 g_W1h[4096u * 4096u];
__device__ f16 g_W2h[4096u * 4096u];
__device__ f16 g_W3h[256 * 4096];
__device__ float g_p3 [16 * 256 * 256];
__device__ float g_pts[256 * 200];

// ---------------- helpers ----------------
__device__ __forceinline__ float sig_apx(float a) {
    float r; asm("tanh.approx.f32 %0,%1;" : "=f"(r) : "f"(a * 0.5f));
    return fmaf(0.5f, r, 0.5f);
}
__device__ __forceinline__ void split_f16(float v, f16& h, f16& l) {
    h = __float2half_rn(v);
    l = __float2half_rn(v - __half2float(h));
}
__device__ __forceinline__ void mma16816(float* c, const uint32_t* a, const uint32_t* b) {
    asm volatile("mma.sync.aligned.m16n8k16.row.col.f32.f16.f16.f32 "
        "{%0,%1,%2,%3}, {%4,%5,%6,%7}, {%8,%9}, {%0,%1,%2,%3};"
        : "+f"(c[0]), "+f"(c[1]), "+f"(c[2]), "+f"(c[3])
        : "r"(a[0]), "r"(a[1]), "r"(a[2]), "r"(a[3]), "r"(b[0]), "r"(b[1]));
}
__device__ __forceinline__ void ldsm4(uint32_t* r, uint32_t addr) {
    asm volatile("ldmatrix.sync.aligned.m8n8.x4.shared.b16 {%0,%1,%2,%3}, [%4];"
        : "=r"(r[0]), "=r"(r[1]), "=r"(r[2]), "=r"(r[3]) : "r"(addr));
}
__device__ __forceinline__ void cpasync16(uint32_t dst, const void* src) {
    asm volatile("cp.async.cg.shared.global [%0], [%1], 16;" :: "r"(dst), "l"(src) : "memory");
}
__device__ __forceinline__ void cpcommit() {
    asm volatile("cp.async.commit_group;" ::: "memory");
}
template<int N> __device__ __forceinline__ void cpwait() {
    asm volatile("cp.async.wait_group %0;" :: "n"(N) : "memory");
}

// ---------------- ECT body (256 threads) ----------------
struct EctSm {
    float xs[200];
    float Vs[128];
    float lins[64];
    float e2[2][4096];
    unsigned char cnt2[2][4096];
    float red[256];
};
#define PREP_SMEM (sizeof(EctSm))

__device__ void ect_body(int g, int tid, const float* __restrict__ pts,
                         const float* __restrict__ V, const float* __restrict__ lin,
                         float* __restrict__ outf, f16* __restrict__ outh,
                         f16* __restrict__ outl, char* sm)
{
    EctSm& S = *reinterpret_cast<EctSm*>(sm);
    if (tid < 64)  S.lins[tid] = lin[tid];
    if (tid < 128) S.Vs[tid] = V[tid];
    if (tid < 100) {
        float2 p = reinterpret_cast<const float2*>(pts)[g * 100 + tid];
        S.xs[2 * tid] = p.x; S.xs[2 * tid + 1] = p.y;
    }
    for (int i = tid; i < 8192; i += 256) (&S.e2[0][0])[i] = 0.0f;
    for (int i = tid; i < 2048; i += 256) reinterpret_cast<int*>(S.cnt2)[i] = 0;
    __syncthreads();

    if (tid < 128) {
        const int t = tid & 63, half = tid >> 6;
        const float vx = S.Vs[t], vy = S.Vs[64 + t];
        float* e = &S.e2[half][t];
        unsigned char* cc = &S.cnt2[half][t];
        const int nbeg = half * 50;
        for (int n = 0; n < 50; ++n) {
            const float x0 = S.xs[2 * (nbeg + n)], x1 = S.xs[2 * (nbeg + n) + 1];
            const float nh = fmaf(x0, vx, x1 * vy);
            const int kf = __float2int_rd((nh + 1.0f) * 31.5f);
            if (kf >= 0 && kf < 64)         e[kf * 64]       += sig_apx(500.0f * (S.lins[kf] - nh));
            if (kf + 1 >= 0 && kf + 1 < 64) e[(kf + 1) * 64] += sig_apx(500.0f * (S.lins[kf + 1] - nh));
            int s = kf + 2; if (s < 0) s = 0;
            if (s < 64) cc[s * 64] = (unsigned char)(cc[s * 64] + 1);
        }
    }
    __syncthreads();

    if (tid < 64) {
        float run = 0.0f;
        for (int k = 0; k < 64; ++k) {
            const int o = k * 64 + tid;
            run += (float)(S.cnt2[0][o] + S.cnt2[1][o]);
            S.e2[0][o] = S.e2[0][o] + S.e2[1][o] + run;
        }
    }
    __syncthreads();

    float mx = 0.0f;
    for (int i = tid; i < 4096; i += 256) mx = fmaxf(mx, S.e2[0][i]);
    S.red[tid] = mx; __syncthreads();
    for (int off = 128; off > 0; off >>= 1) {
        if (tid < off) S.red[tid] = fmaxf(S.red[tid], S.red[tid + off]);
        __syncthreads();
    }
    const float inv = 1.0f / S.red[0];
    for (int i = tid; i < 4096; i += 256) {
        float v = S.e2[0][i] * inv;
        if (outf) outf[(long)g * 4096 + i] = v;
        if (outh) {
            f16 h, l; split_f16(v, h, l);
            outh[(long)g * 4096 + i] = h;
            outl[(long)g * 4096 + i] = l;
        }
    }
}

// ---------------- transpose body: W[k][n] -> T[n][k] fp16 ----------------
__device__ void transpose_body(int kt, int ntile, int tid, const float* __restrict__ W,
                               int Wn, f16* __restrict__ Th, char* sm)
{
    float (*s)[65] = reinterpret_cast<float(*)[65]>(sm);
    const int k0 = kt * 64, n0 = ntile * 64;
    const int r = tid >> 4, c4 = (tid & 15) * 4;
    #pragma unroll
    for (int p = 0; p < 4; ++p) {
        const int kk = p * 16 + r;
        float4 v;
        if (Wn == 4096) {
            v = *reinterpret_cast<const float4*>(W + (long)(k0 + kk) * 4096 + n0 + c4);
        } else {
            float t0 = 0, t1 = 0, t2 = 0, t3 = 0;
            const long base = (long)(k0 + kk) * 200;
            if (n0 + c4 + 0 < 200) t0 = W[base + n0 + c4 + 0];
            if (n0 + c4 + 1 < 200) t1 = W[base + n0 + c4 + 1];
            if (n0 + c4 + 2 < 200) t2 = W[base + n0 + c4 + 2];
            if (n0 + c4 + 3 < 200) t3 = W[base + n0 + c4 + 3];
            v = make_float4(t0, t1, t2, t3);
        }
        s[kk][c4] = v.x; s[kk][c4 + 1] = v.y; s[kk][c4 + 2] = v.z; s[kk][c4 + 3] = v.w;
    }
    __syncthreads();
    #pragma unroll
    for (int q = 0; q < 2; ++q) {
        const int idx = tid + 256 * q;
        const int n = idx >> 3, kg = idx & 7;
        uint4 uh;
        __half2* ph = reinterpret_cast<__half2*>(&uh);
        #pragma unroll
        for (int j = 0; j < 4; ++j) {
            ph[j] = __floats2half2_rn(s[kg * 8 + 2 * j][n], s[kg * 8 + 2 * j + 1][n]);
        }
        const long o = (long)(n0 + n) * 4096 + k0 + kg * 8;
        *reinterpret_cast<uint4*>(Th + o) = uh;
    }
}

// ---------------- fused prep ----------------
__global__ void __launch_bounds__(256) prep_all(const float* __restrict__ x,
    const float* __restrict__ V, const float* __restrict__ lin,
    const float* __restrict__ W1, const float* __restrict__ W2, const float* __restrict__ W3,
    f16* W1h, f16* W2h, f16* W3h, f16* Ah, f16* Al)
{
    extern __shared__ char sm[];
    int b = blockIdx.x;
    const int tid = threadIdx.x;
    if (b < 4096)       transpose_body(b & 63, b >> 6, tid, W1, 4096, W1h, sm);
    else if (b < 8192) { b -= 4096; transpose_body(b & 63, b >> 6, tid, W2, 4096, W2h, sm); }
    else if (b < 8448) { b -= 8192; transpose_body(b & 63, b >> 6, tid, W3,  200, W3h, sm); }
    else                ect_body(b - 8448, tid, x, V, lin, nullptr, Ah, Al, sm);
}

__global__ void __launch_bounds__(256) ect_final(const float* __restrict__ pts,
    const float* __restrict__ V, const float* __restrict__ lin, float* __restrict__ out)
{
    extern __shared__ char sm[];
    ect_body(blockIdx.x, threadIdx.x, pts, V, lin, out, nullptr, nullptr, sm);
}

// ---------------- HMMA GEMM: fp16 2-product (Ah+Al)*Bh, 4-stage cp.async ----------------
// CTA 64x128, BK=64, 8 warps (2x4), warp 32x32. Stage: Ah 8K | Al 8K | Bh 16K.
#define STG 32768
#define NSTAGE 4
#define GMEM_SM (NSTAGE * STG)

template<int KT, bool TANH>
__global__ void __launch_bounds__(256) gemm_mma(const f16* __restrict__ Ah,
                                                const f16* __restrict__ Al,
                                                const f16* __restrict__ Bh,
                                                const float* __restrict__ bias,
                                                f16* __restrict__ oH,
                                                f16* __restrict__ oL,
                                                float* __restrict__ oP)
{
    extern __shared__ __align__(16) char dsm[];
    const uint32_t smem0 = (uint32_t)__cvta_generic_to_shared(dsm);
    const int tid = threadIdx.x;
    const int lane = tid & 31, wid = tid >> 5;
    const int wm = wid >> 2, wn = wid & 3;
    const int m0 = blockIdx.x * 64, n0 = blockIdx.y * 128;
    const long kOff = TANH ? 0 : (long)blockIdx.z * (KT * 64);

    const int r0 = tid >> 3, kq = tid & 7;
    const uint32_t dsw = (uint32_t)(r0 * 128 + ((kq * 16) ^ ((r0 & 7) << 4)));
    const f16* pAh = Ah + (long)(m0 + r0) * 4096 + kOff + kq * 8;
    const f16* pAl = Al + (long)(m0 + r0) * 4096 + kOff + kq * 8;
    const f16* pBh = Bh + (long)(n0 + r0) * 4096 + kOff + kq * 8;

    float acc[2][4][4];
    #pragma unroll
    for (int a = 0; a < 2; ++a)
        #pragma unroll
        for (int b = 0; b < 4; ++b)
            #pragma unroll
            for (int c = 0; c < 4; ++c) acc[a][b][c] = 0.0f;

    const int lr = lane & 7, lt = lane >> 3;
    const uint32_t aRow = (uint32_t)((wm * 32 + ((lt & 1) << 3) + lr) * 128);
    const int aK = (lt >> 1) * 16;
    const uint32_t bRow = (uint32_t)((wn * 32 + ((lt >> 1) << 3) + lr) * 128);
    const int bK = (lt & 1) * 16;
    const int sw = lr << 4;

    auto load_stage = [&](int stg, int kt) {
        const uint32_t st = smem0 + stg * STG;
        const long g = (long)kt * 64;
        #pragma unroll
        for (int i = 0; i < 2; ++i) {
            cpasync16(st + dsw + i * 32 * 128,        pAh + g + (long)i * 32 * 4096);
            cpasync16(st + 8192 + dsw + i * 32 * 128, pAl + g + (long)i * 32 * 4096);
        }
        #pragma unroll
        for (int i = 0; i < 4; ++i) {
            cpasync16(st + 16384 + dsw + i * 32 * 128, pBh + g + (long)i * 32 * 4096);
        }
    };

    #pragma unroll
    for (int s = 0; s < NSTAGE - 1; ++s) {
        if (s < KT) load_stage(s, s);
        cpcommit();
    }

    for (int kt = 0; kt < KT; ++kt) {
        if (kt + NSTAGE - 1 < KT) load_stage((kt + NSTAGE - 1) & (NSTAGE - 1), kt + NSTAGE - 1);
        cpcommit();
        cpwait<NSTAGE - 1>();
        __syncthreads();

        const uint32_t st = smem0 + (kt & (NSTAGE - 1)) * STG;
        #pragma unroll
        for (int ks = 0; ks < 4; ++ks) {
            const int ka = (ks * 32 + aK) ^ sw;
            const int kb = (ks * 32 + bK) ^ sw;
            uint32_t fAh[2][4], fAl[2][4], fBh[2][4];
            ldsm4(fAh[0], st + aRow + ka);
            ldsm4(fAh[1], st + aRow + 16 * 128 + ka);
            ldsm4(fAl[0], st + 8192 + aRow + ka);
            ldsm4(fAl[1], st + 8192 + aRow + 16 * 128 + ka);
            ldsm4(fBh[0], st + 16384 + bRow + kb);
            ldsm4(fBh[1], st + 16384 + bRow + 16 * 128 + kb);
            #pragma unroll
            for (int mt = 0; mt < 2; ++mt)
                #pragma unroll
                for (int nt = 0; nt < 4; ++nt) {
                    const uint32_t* bh = &fBh[nt >> 1][(nt & 1) * 2];
                    mma16816(acc[mt][nt], fAh[mt], bh);
                    mma16816(acc[mt][nt], fAl[mt], bh);
                }
        }
    }

    const int laneR = lane >> 2;
    #pragma unroll
    for (int mt = 0; mt < 2; ++mt)
        #pragma unroll
        for (int nt = 0; nt < 4; ++nt) {
            const int rr = m0 + wm * 32 + mt * 16 + laneR;
            const int nc = n0 + wn * 32 + nt * 8 + 2 * (lane & 3);
            if (TANH) {
                const float b0 = bias[nc], b1 = bias[nc + 1];
                float v00 = tanhf(acc[mt][nt][0] + b0);
                float v01 = tanhf(acc[mt][nt][1] + b1);
                float v10 = tanhf(acc[mt][nt][2] + b0);
                float v11 = tanhf(acc[mt][nt][3] + b1);
                f16 h00, l00, h01, l01, h10, l10, h11, l11;
                split_f16(v00, h00, l00); split_f16(v01, h01, l01);
                split_f16(v10, h10, l10); split_f16(v11, h11, l11);
                *(__half2*)(oH + (long)rr * 4096 + nc)       = __halves2half2(h00, h01);
                *(__half2*)(oH + (long)(rr + 8) * 4096 + nc) = __halves2half2(h10, h11);
                *(__half2*)(oL + (long)rr * 4096 + nc)       = __halves2half2(l00, l01);
                *(__half2*)(oL + (long)(rr + 8) * 4096 + nc) = __halves2half2(l10, l11);
            } else {
                float* P = oP + (long)blockIdx.z * 65536;
                *(float2*)(P + (long)rr * 256 + nc)       = make_float2(acc[mt][nt][0], acc[mt][nt][1]);
                *(float2*)(P + (long)(rr + 8) * 256 + nc) = make_float2(acc[mt][nt][2], acc[mt][nt][3]);
            }
        }
}

// ---------------- reduce ----------------
__global__ void reduce_pts(const float* __restrict__ P, const float* __restrict__ b3,
                           float* __restrict__ pts, float* __restrict__ otail)
{
    const int i = blockIdx.x * 256 + threadIdx.x;
    const int m = i >> 8, n = i & 255;
    if (n >= 200) return;
    float s = b3[n];
    #pragma unroll
    for (int zz = 0; zz < 16; ++zz) s += P[zz * 65536 + i];
    pts[m * 200 + n] = s;
    otail[m * 200 + n] = s;
}

// ---------------- launch ----------------
extern "C" void kernel_launch(void* const* d_in, const int* in_sizes, int n_in,
                              void* d_out, int out_size)
{
    const float* x   = (const float*)d_in[0];
    const float* V   = (const float*)d_in[2];
    const float* lin = (const float*)d_in[3];
    const float* W1  = (const float*)d_in[4];
    const float* b1  = (const float*)d_in[5];
    const float* W2  = (const float*)d_in[6];
    const float* b2  = (const float*)d_in[7];
    const float* W3  = (const float*)d_in[8];
    const float* b3  = (const float*)d_in[9];
    float* out = (float*)d_out;

    f16 *Ah, *Al, *Ah2, *Al2, *Ah3, *Al3, *W1h, *W2h, *W3h;
    float *p3, *pts;
    cudaGetSymbolAddress((void**)&Ah,  g_Ah);
    cudaGetSymbolAddress((void**)&Al,  g_Al);
    cudaGetSymbolAddress((void**)&Ah2, g_Ah2);
    cudaGetSymbolAddress((void**)&Al2, g_Al2);
    cudaGetSymbolAddress((void**)&Ah3, g_Ah3);
    cudaGetSymbolAddress((void**)&Al3, g_Al3);
    cudaGetSymbolAddress((void**)&W1h, g_W1h);
    cudaGetSymbolAddress((void**)&W2h, g_W2h);
    cudaGetSymbolAddress((void**)&W3h, g_W3h);
    cudaGetSymbolAddress((void**)&p3,  g_p3);
    cudaGetSymbolAddress((void**)&pts, g_pts);

    const int prep_sm = (int)PREP_SMEM;
    cudaFuncSetAttribute(prep_all,  cudaFuncAttributeMaxDynamicSharedMemorySize, prep_sm);
    cudaFuncSetAttribute(ect_final, cudaFuncAttributeMaxDynamicSharedMemorySize, prep_sm);
    cudaFuncSetAttribute(gemm_mma<64, true>,  cudaFuncAttributeMaxDynamicSharedMemorySize, GMEM_SM);
    cudaFuncSetAttribute(gemm_mma<4, false>,  cudaFuncAttributeMaxDynamicSharedMemorySize, GMEM_SM);

    prep_all<<<8704, 256, prep_sm>>>(x, V, lin, W1, W2, W3,
                                     W1h, W2h, W3h, Ah, Al);

    gemm_mma<64, true><<<dim3(4, 32), 256, GMEM_SM>>>(Ah,  Al,  W1h, b1, Ah2, Al2, nullptr);
    gemm_mma<64, true><<<dim3(4, 32), 256, GMEM_SM>>>(Ah2, Al2, W2h, b2, Ah3, Al3, nullptr);
    gemm_mma<4, false><<<dim3(4, 2, 16), 256, GMEM_SM>>>(Ah3, Al3, W3h, nullptr, nullptr, nullptr, p3);

    reduce_pts<<<256, 256>>>(p3, b3, pts, out + 256 * 64 * 64);
    ect_final<<<256, 256, prep_sm>>>(pts, V, lin, out);
}

// round 9
// speedup vs baseline: 1.6245x; 1.2907x over previous
#include <cuda_runtime.h>
#include <cuda_fp16.h>
#include <cstdint>

typedef __half f16;

// ---------------- scratch ----------------
__device__ f16 g_A1 [256 * 4096];
__device__ f16 g_A2 [256 * 4096];
__device__ f16 g_A3 [256 * 4096];
__device__ f16 g_W1h[4096u * 4096u];
__device__ f16 g_W2h[4096u * 4096u];
__device__ f16 g_W3h[256 * 4096];
__device__ float g_p3 [16 * 256 * 256];
__device__ float g_pts[256 * 200];

// ---------------- helpers ----------------
__device__ __forceinline__ float sig_apx(float a) {
    float r; asm("tanh.approx.f32 %0,%1;" : "=f"(r) : "f"(a * 0.5f));
    return fmaf(0.5f, r, 0.5f);
}
__device__ __forceinline__ void mma16816(float* c, const uint32_t* a, const uint32_t* b) {
    asm volatile("mma.sync.aligned.m16n8k16.row.col.f32.f16.f16.f32 "
        "{%0,%1,%2,%3}, {%4,%5,%6,%7}, {%8,%9}, {%0,%1,%2,%3};"
        : "+f"(c[0]), "+f"(c[1]), "+f"(c[2]), "+f"(c[3])
        : "r"(a[0]), "r"(a[1]), "r"(a[2]), "r"(a[3]), "r"(b[0]), "r"(b[1]));
}
__device__ __forceinline__ void ldsm4(uint32_t* r, uint32_t addr) {
    asm volatile("ldmatrix.sync.aligned.m8n8.x4.shared.b16 {%0,%1,%2,%3}, [%4];"
        : "=r"(r[0]), "=r"(r[1]), "=r"(r[2]), "=r"(r[3]) : "r"(addr));
}
__device__ __forceinline__ void cpasync16(uint32_t dst, const void* src) {
    asm volatile("cp.async.cg.shared.global [%0], [%1], 16;" :: "r"(dst), "l"(src) : "memory");
}
__device__ __forceinline__ void cpcommit() {
    asm volatile("cp.async.commit_group;" ::: "memory");
}
template<int N> __device__ __forceinline__ void cpwait() {
    asm volatile("cp.async.wait_group %0;" :: "n"(N) : "memory");
}

// ---------------- ECT body (256 threads, 4 node-quarters) ----------------
struct EctSm {
    float xs[200];
    float Vs[128];
    float lins[64];
    float e2[4][4096];
    unsigned char cnt2[4][4096];
    float red[256];
};
#define PREP_SMEM (sizeof(EctSm))

__device__ void ect_body(int g, int tid, const float* __restrict__ pts,
                         const float* __restrict__ V, const float* __restrict__ lin,
                         float* __restrict__ outf, f16* __restrict__ outh, char* sm)
{
    EctSm& S = *reinterpret_cast<EctSm*>(sm);
    if (tid < 64)  S.lins[tid] = lin[tid];
    if (tid < 128) S.Vs[tid] = V[tid];
    if (tid < 100) {
        float2 p = reinterpret_cast<const float2*>(pts)[g * 100 + tid];
        S.xs[2 * tid] = p.x; S.xs[2 * tid + 1] = p.y;
    }
    for (int i = tid; i < 16384; i += 256) (&S.e2[0][0])[i] = 0.0f;
    for (int i = tid; i < 4096; i += 256) reinterpret_cast<int*>(S.cnt2)[i] = 0;
    __syncthreads();

    {
        const int t = tid & 63, q = tid >> 6;     // quarter 0..3
        const float vx = S.Vs[t], vy = S.Vs[64 + t];
        float* e = &S.e2[q][t];
        unsigned char* cc = &S.cnt2[q][t];
        const int nbeg = q * 25;
        for (int n = 0; n < 25; ++n) {
            const float x0 = S.xs[2 * (nbeg + n)], x1 = S.xs[2 * (nbeg + n) + 1];
            const float nh = fmaf(x0, vx, x1 * vy);
            const int kf = __float2int_rd((nh + 1.0f) * 31.5f);
            if (kf >= 0 && kf < 64)         e[kf * 64]       += sig_apx(500.0f * (S.lins[kf] - nh));
            if (kf + 1 >= 0 && kf + 1 < 64) e[(kf + 1) * 64] += sig_apx(500.0f * (S.lins[kf + 1] - nh));
            int s = kf + 2; if (s < 0) s = 0;
            if (s < 64) cc[s * 64] = (unsigned char)(cc[s * 64] + 1);
        }
    }
    __syncthreads();

    if (tid < 64) {
        float run = 0.0f;
        for (int k = 0; k < 64; ++k) {
            const int o = k * 64 + tid;
            run += (float)(S.cnt2[0][o] + S.cnt2[1][o] + S.cnt2[2][o] + S.cnt2[3][o]);
            S.e2[0][o] = S.e2[0][o] + S.e2[1][o] + S.e2[2][o] + S.e2[3][o] + run;
        }
    }
    __syncthreads();

    float mx = 0.0f;
    for (int i = tid; i < 4096; i += 256) mx = fmaxf(mx, S.e2[0][i]);
    S.red[tid] = mx; __syncthreads();
    for (int off = 128; off > 0; off >>= 1) {
        if (tid < off) S.red[tid] = fmaxf(S.red[tid], S.red[tid + off]);
        __syncthreads();
    }
    const float inv = 1.0f / S.red[0];
    for (int i = tid; i < 4096; i += 256) {
        float v = S.e2[0][i] * inv;
        if (outf) outf[(long)g * 4096 + i] = v;
        if (outh) outh[(long)g * 4096 + i] = __float2half_rn(v);
    }
}

// ---------------- transpose body: W[k][n] -> T[n][k] fp16 ----------------
__device__ void transpose_body(int kt, int ntile, int tid, const float* __restrict__ W,
                               int Wn, f16* __restrict__ Th, char* sm)
{
    float (*s)[65] = reinterpret_cast<float(*)[65]>(sm);
    const int k0 = kt * 64, n0 = ntile * 64;
    const int r = tid >> 4, c4 = (tid & 15) * 4;
    #pragma unroll
    for (int p = 0; p < 4; ++p) {
        const int kk = p * 16 + r;
        float4 v;
        if (Wn == 4096) {
            v = *reinterpret_cast<const float4*>(W + (long)(k0 + kk) * 4096 + n0 + c4);
        } else {
            float t0 = 0, t1 = 0, t2 = 0, t3 = 0;
            const long base = (long)(k0 + kk) * 200;
            if (n0 + c4 + 0 < 200) t0 = W[base + n0 + c4 + 0];
            if (n0 + c4 + 1 < 200) t1 = W[base + n0 + c4 + 1];
            if (n0 + c4 + 2 < 200) t2 = W[base + n0 + c4 + 2];
            if (n0 + c4 + 3 < 200) t3 = W[base + n0 + c4 + 3];
            v = make_float4(t0, t1, t2, t3);
        }
        s[kk][c4] = v.x; s[kk][c4 + 1] = v.y; s[kk][c4 + 2] = v.z; s[kk][c4 + 3] = v.w;
    }
    __syncthreads();
    #pragma unroll
    for (int q = 0; q < 2; ++q) {
        const int idx = tid + 256 * q;
        const int n = idx >> 3, kg = idx & 7;
        uint4 uh;
        __half2* ph = reinterpret_cast<__half2*>(&uh);
        #pragma unroll
        for (int j = 0; j < 4; ++j) {
            ph[j] = __floats2half2_rn(s[kg * 8 + 2 * j][n], s[kg * 8 + 2 * j + 1][n]);
        }
        const long o = (long)(n0 + n) * 4096 + k0 + kg * 8;
        *reinterpret_cast<uint4*>(Th + o) = uh;
    }
}

// ---------------- fused prep ----------------
__global__ void __launch_bounds__(256) prep_all(const float* __restrict__ x,
    const float* __restrict__ V, const float* __restrict__ lin,
    const float* __restrict__ W1, const float* __restrict__ W2, const float* __restrict__ W3,
    f16* W1h, f16* W2h, f16* W3h, f16* A1)
{
    extern __shared__ char sm[];
    int b = blockIdx.x;
    const int tid = threadIdx.x;
    if (b < 4096)       transpose_body(b & 63, b >> 6, tid, W1, 4096, W1h, sm);
    else if (b < 8192) { b -= 4096; transpose_body(b & 63, b >> 6, tid, W2, 4096, W2h, sm); }
    else if (b < 8448) { b -= 8192; transpose_body(b & 63, b >> 6, tid, W3,  200, W3h, sm); }
    else                ect_body(b - 8448, tid, x, V, lin, nullptr, A1, sm);
}

__global__ void __launch_bounds__(256) ect_final(const float* __restrict__ pts,
    const float* __restrict__ V, const float* __restrict__ lin, float* __restrict__ out)
{
    extern __shared__ char sm[];
    ect_body(blockIdx.x, threadIdx.x, pts, V, lin, out, nullptr, sm);
}

// ---------------- HMMA GEMM: fp16 single-product A*Bh, 4-stage cp.async ----------------
// CTA 64x128, BK=64, 8 warps (2x4), warp 32x32. Stage: A 8K | Bh 16K.
#define STG 24576
#define NSTAGE 4
#define GMEM_SM (NSTAGE * STG)

template<int KT, bool TANH>
__global__ void __launch_bounds__(256) gemm_mma(const f16* __restrict__ A,
                                                const f16* __restrict__ Bh,
                                                const float* __restrict__ bias,
                                                f16* __restrict__ oH,
                                                float* __restrict__ oP)
{
    extern __shared__ __align__(16) char dsm[];
    const uint32_t smem0 = (uint32_t)__cvta_generic_to_shared(dsm);
    const int tid = threadIdx.x;
    const int lane = tid & 31, wid = tid >> 5;
    const int wm = wid >> 2, wn = wid & 3;
    const int m0 = blockIdx.x * 64, n0 = blockIdx.y * 128;
    const long kOff = TANH ? 0 : (long)blockIdx.z * (KT * 64);

    const int r0 = tid >> 3, kq = tid & 7;
    const uint32_t dsw = (uint32_t)(r0 * 128 + ((kq * 16) ^ ((r0 & 7) << 4)));
    const f16* pA  = A  + (long)(m0 + r0) * 4096 + kOff + kq * 8;
    const f16* pBh = Bh + (long)(n0 + r0) * 4096 + kOff + kq * 8;

    float acc[2][4][4];
    #pragma unroll
    for (int a = 0; a < 2; ++a)
        #pragma unroll
        for (int b = 0; b < 4; ++b)
            #pragma unroll
            for (int c = 0; c < 4; ++c) acc[a][b][c] = 0.0f;

    const int lr = lane & 7, lt = lane >> 3;
    const uint32_t aRow = (uint32_t)((wm * 32 + ((lt & 1) << 3) + lr) * 128);
    const int aK = (lt >> 1) * 16;
    const uint32_t bRow = (uint32_t)((wn * 32 + ((lt >> 1) << 3) + lr) * 128);
    const int bK = (lt & 1) * 16;
    const int sw = lr << 4;

    auto load_stage = [&](int stg, int kt) {
        const uint32_t st = smem0 + stg * STG;
        const long g = (long)kt * 64;
        #pragma unroll
        for (int i = 0; i < 2; ++i) {
            cpasync16(st + dsw + i * 32 * 128, pA + g + (long)i * 32 * 4096);
        }
        #pragma unroll
        for (int i = 0; i < 4; ++i) {
            cpasync16(st + 8192 + dsw + i * 32 * 128, pBh + g + (long)i * 32 * 4096);
        }
    };

    #pragma unroll
    for (int s = 0; s < NSTAGE - 1; ++s) {
        if (s < KT) load_stage(s, s);
        cpcommit();
    }

    for (int kt = 0; kt < KT; ++kt) {
        if (kt + NSTAGE - 1 < KT) load_stage((kt + NSTAGE - 1) & (NSTAGE - 1), kt + NSTAGE - 1);
        cpcommit();
        cpwait<NSTAGE - 1>();
        __syncthreads();

        const uint32_t st = smem0 + (kt & (NSTAGE - 1)) * STG;
        #pragma unroll
        for (int ks = 0; ks < 4; ++ks) {
            const int ka = (ks * 32 + aK) ^ sw;
            const int kb = (ks * 32 + bK) ^ sw;
            uint32_t fA[2][4], fBh[2][4];
            ldsm4(fA[0], st + aRow + ka);
            ldsm4(fA[1], st + aRow + 16 * 128 + ka);
            ldsm4(fBh[0], st + 8192 + bRow + kb);
            ldsm4(fBh[1], st + 8192 + bRow + 16 * 128 + kb);
            #pragma unroll
            for (int mt = 0; mt < 2; ++mt)
                #pragma unroll
                for (int nt = 0; nt < 4; ++nt) {
                    const uint32_t* bh = &fBh[nt >> 1][(nt & 1) * 2];
                    mma16816(acc[mt][nt], fA[mt], bh);
                }
        }
    }

    const int laneR = lane >> 2;
    #pragma unroll
    for (int mt = 0; mt < 2; ++mt)
        #pragma unroll
        for (int nt = 0; nt < 4; ++nt) {
            const int rr = m0 + wm * 32 + mt * 16 + laneR;
            const int nc = n0 + wn * 32 + nt * 8 + 2 * (lane & 3);
            if (TANH) {
                const float b0 = bias[nc], b1 = bias[nc + 1];
                float v00 = tanhf(acc[mt][nt][0] + b0);
                float v01 = tanhf(acc[mt][nt][1] + b1);
                float v10 = tanhf(acc[mt][nt][2] + b0);
                float v11 = tanhf(acc[mt][nt][3] + b1);
                *(__half2*)(oH + (long)rr * 4096 + nc)       = __floats2half2_rn(v00, v01);
                *(__half2*)(oH + (long)(rr + 8) * 4096 + nc) = __floats2half2_rn(v10, v11);
            } else {
                float* P = oP + (long)blockIdx.z * 65536;
                *(float2*)(P + (long)rr * 256 + nc)       = make_float2(acc[mt][nt][0], acc[mt][nt][1]);
                *(float2*)(P + (long)(rr + 8) * 256 + nc) = make_float2(acc[mt][nt][2], acc[mt][nt][3]);
            }
        }
}

// ---------------- reduce ----------------
__global__ void reduce_pts(const float* __restrict__ P, const float* __restrict__ b3,
                           float* __restrict__ pts, float* __restrict__ otail)
{
    const int i = blockIdx.x * 256 + threadIdx.x;
    const int m = i >> 8, n = i & 255;
    if (n >= 200) return;
    float s = b3[n];
    #pragma unroll
    for (int zz = 0; zz < 16; ++zz) s += P[zz * 65536 + i];
    pts[m * 200 + n] = s;
    otail[m * 200 + n] = s;
}

// ---------------- launch ----------------
extern "C" void kernel_launch(void* const* d_in, const int* in_sizes, int n_in,
                              void* d_out, int out_size)
{
    const float* x   = (const float*)d_in[0];
    const float* V   = (const float*)d_in[2];
    const float* lin = (const float*)d_in[3];
    const float* W1  = (const float*)d_in[4];
    const float* b1  = (const float*)d_in[5];
    const float* W2  = (const float*)d_in[6];
    const float* b2  = (const float*)d_in[7];
    const float* W3  = (const float*)d_in[8];
    const float* b3  = (const float*)d_in[9];
    float* out = (float*)d_out;

    f16 *A1, *A2, *A3, *W1h, *W2h, *W3h;
    float *p3, *pts;
    cudaGetSymbolAddress((void**)&A1,  g_A1);
    cudaGetSymbolAddress((void**)&A2,  g_A2);
    cudaGetSymbolAddress((void**)&A3,  g_A3);
    cudaGetSymbolAddress((void**)&W1h, g_W1h);
    cudaGetSymbolAddress((void**)&W2h, g_W2h);
    cudaGetSymbolAddress((void**)&W3h, g_W3h);
    cudaGetSymbolAddress((void**)&p3,  g_p3);
    cudaGetSymbolAddress((void**)&pts, g_pts);

    const int prep_sm = (int)PREP_SMEM;
    cudaFuncSetAttribute(prep_all,  cudaFuncAttributeMaxDynamicSharedMemorySize, prep_sm);
    cudaFuncSetAttribute(ect_final, cudaFuncAttributeMaxDynamicSharedMemorySize, prep_sm);
    cudaFuncSetAttribute(gemm_mma<64, true>,  cudaFuncAttributeMaxDynamicSharedMemorySize, GMEM_SM);
    cudaFuncSetAttribute(gemm_mma<4, false>,  cudaFuncAttributeMaxDynamicSharedMemorySize, GMEM_SM);

    prep_all<<<8704, 256, prep_sm>>>(x, V, lin, W1, W2, W3, W1h, W2h, W3h, A1);

    gemm_mma<64, true><<<dim3(4, 32), 256, GMEM_SM>>>(A1, W1h, b1, A2, nullptr);
    gemm_mma<64, true><<<dim3(4, 32), 256, GMEM_SM>>>(A2, W2h, b2, A3, nullptr);
    gemm_mma<4, false><<<dim3(4, 2, 16), 256, GMEM_SM>>>(A3, W3h, nullptr, nullptr, p3);

    reduce_pts<<<256, 256>>>(p3, b3, pts, out + 256 * 64 * 64);
    ect_final<<<256, 256, prep_sm>>>(pts, V, lin, out);
}